// round 6
// baseline (speedup 1.0000x reference)
#include <cuda_runtime.h>
#include <cuda_bf16.h>
#include <cstdint>

#define N_NODES 4096
#define HIDDEN  64
#define N_REL   8
#define N_LAYERS 2
#define NH (N_NODES * HIDDEN)

// ---------------------------------------------------------------- helpers
__device__ __forceinline__ uint32_t smem_u32(const void* p) {
    uint32_t a;
    asm("{ .reg .u64 t; cvta.to.shared.u64 t, %1; cvt.u32.u64 %0, t; }" : "=r"(a) : "l"(p));
    return a;
}

#define LDSM4(r, addr) \
    asm volatile("ldmatrix.sync.aligned.m8n8.x4.shared.b16 {%0,%1,%2,%3}, [%4];" \
        : "=r"((r)[0]), "=r"((r)[1]), "=r"((r)[2]), "=r"((r)[3]) : "r"(addr))

// int8 MMA: D(s32) += A(s8,16x32) * B(s8,32x8)
#define MMAI8(c, a, b0, b1) \
    asm volatile("mma.sync.aligned.m16n8k32.row.col.s32.s8.s8.s32 " \
        "{%0,%1,%2,%3}, {%4,%5,%6,%7}, {%8,%9}, {%0,%1,%2,%3};" \
        : "+r"((c)[0]), "+r"((c)[1]), "+r"((c)[2]), "+r"((c)[3]) \
        : "r"((a)[0]), "r"((a)[1]), "r"((a)[2]), "r"((a)[3]), "r"(b0), "r"(b1))

#define LDGSTS16(dst, src) \
    asm volatile("cp.async.cg.shared.global [%0], [%1], 16;" :: "r"(dst), "l"(src))
#define CP_COMMIT() asm volatile("cp.async.commit_group;" ::: "memory")
#define CP_WAIT1() asm volatile("cp.async.wait_group 1;" ::: "memory")
#define CP_WAIT0() asm volatile("cp.async.wait_group 0;" ::: "memory")

// ---------------------------------------------------------------- scratch
__device__ float g_h[2][NH];
__device__ float g_S[NH];
__device__ float g_part[N_REL][NH];
__device__ float g_Yt[N_REL * HIDDEN * N_NODES];          // Y^T fp32 [r][e][m]
__device__ int8_t g_Yqh[N_REL * HIDDEN * N_NODES];        // Y^T hi limb
__device__ int8_t g_Yql[N_REL * HIDDEN * N_NODES];        // Y^T lo limb
__device__ float g_scale[N_REL * HIDDEN];                 // s_e/(32512*32768)
__device__ float g_corr[N_REL * HIDDEN];                  // 128*colsum*scale
__device__ int8_t g_Ah[(size_t)N_REL * N_NODES * N_NODES];  // adj hi limb
__device__ int8_t g_Al[(size_t)N_REL * N_NODES * N_NODES];  // adj lo limb (byte = (q&255)^0x80)

// ---------------------------------------------------------------- init copy
__global__ void copy_init_kernel(float* __restrict__ dst, const float* __restrict__ src) {
    int i = blockIdx.x * blockDim.x + threadIdx.x;
    if (i < NH / 4) ((float4*)dst)[i] = ((const float4*)src)[i];
}

// ---------------------------------------------------------------- adj -> s8 limbs (ONCE)
// a in [0,1): q = clamp(rint(a*32768), 0, 32767); ah = q>>8; al byte = (q&255)^0x80 (s8 = (q&255)-128)
__global__ void __launch_bounds__(256) convert_adj_kernel(
    const float* __restrict__ adj,
    uint32_t* __restrict__ Ah,
    uint32_t* __restrict__ Al)
{
    size_t base = ((size_t)blockIdx.x * 256 + threadIdx.x) * 16;
    const float4* fp = (const float4*)(adj + base);
    uint32_t hw[4], lw[4];
    #pragma unroll
    for (int i = 0; i < 4; i++) {
        float4 f = fp[i];
        int q0 = min(32767, __float2int_rn(f.x * 32768.f));
        int q1 = min(32767, __float2int_rn(f.y * 32768.f));
        int q2 = min(32767, __float2int_rn(f.z * 32768.f));
        int q3 = min(32767, __float2int_rn(f.w * 32768.f));
        hw[i] = (uint32_t)(q0 >> 8) | ((uint32_t)(q1 >> 8) << 8) |
                ((uint32_t)(q2 >> 8) << 16) | ((uint32_t)(q3 >> 8) << 24);
        lw[i] = ((uint32_t)(q0 & 255) | ((uint32_t)(q1 & 255) << 8) |
                 ((uint32_t)(q2 & 255) << 16) | ((uint32_t)(q3 & 255) << 24)) ^ 0x80808080u;
    }
    *(uint4*)(Ah + base / 4) = make_uint4(hw[0], hw[1], hw[2], hw[3]);
    *(uint4*)(Al + base / 4) = make_uint4(lw[0], lw[1], lw[2], lw[3]);
}

// ---------------------------------------------------------------- Y / S
// wi<8: Yt fp32 [wi][e][m] ; wi==8: S = h @ w_self fp32
__global__ void __launch_bounds__(256) compute_ys_kernel(
    const float* __restrict__ h,
    const float* __restrict__ w_self,
    const float* __restrict__ w_rel,
    int layer,
    float* __restrict__ Yt,
    float* __restrict__ S)
{
    __shared__ float Ws[HIDDEN * HIDDEN];
    __shared__ float Hs[64 * HIDDEN];

    int m0 = blockIdx.x * 64;
    int wi = blockIdx.y;
    const float* W = (wi < N_REL)
        ? (w_rel + ((size_t)layer * N_REL + wi) * HIDDEN * HIDDEN)
        : (w_self + (size_t)layer * HIDDEN * HIDDEN);

    int tid = threadIdx.x;
    const float4* Wg = (const float4*)W;
    const float4* Hg = (const float4*)(h + (size_t)m0 * HIDDEN);
    for (int i = tid; i < 1024; i += 256) {
        ((float4*)Ws)[i] = Wg[i];
        ((float4*)Hs)[i] = Hg[i];
    }
    __syncthreads();

    int tx = tid & 15, ty = tid >> 4;
    int e0 = tx * 4;
    #pragma unroll
    for (int mi = 0; mi < 4; mi++) {
        int m = ty * 4 + mi;
        float4 acc = make_float4(0.f, 0.f, 0.f, 0.f);
        #pragma unroll
        for (int d = 0; d < HIDDEN; d++) {
            float hv = Hs[m * HIDDEN + d];
            float4 wv = *(const float4*)&Ws[d * HIDDEN + e0];
            acc.x = fmaf(hv, wv.x, acc.x);
            acc.y = fmaf(hv, wv.y, acc.y);
            acc.z = fmaf(hv, wv.z, acc.z);
            acc.w = fmaf(hv, wv.w, acc.w);
        }
        int mg = m0 + m;
        if (wi < N_REL) {
            float v[4] = {acc.x, acc.y, acc.z, acc.w};
            #pragma unroll
            for (int j = 0; j < 4; j++)
                Yt[((size_t)wi * HIDDEN + (e0 + j)) * N_NODES + mg] = v[j];
        } else {
            *(float4*)&S[(size_t)mg * HIDDEN + e0] = acc;
        }
    }
}

// ---------------------------------------------------------------- Y quantization
// one block per (r,e) column: s = max|y|; iv = rint(y/s*32512); yh=(iv+128)>>8; yl=iv-256*yh
__global__ void __launch_bounds__(256) quant_y_kernel(
    const float* __restrict__ Yt,
    int8_t* __restrict__ qh, int8_t* __restrict__ ql,
    float* __restrict__ sc, float* __restrict__ cr)
{
    __shared__ float smax[256];
    __shared__ int ssum[256];
    int re = blockIdx.x;
    int tid = threadIdx.x;
    const float4* rp = (const float4*)(Yt + (size_t)re * N_NODES + tid * 16);

    float4 v[4];
    float mx = 0.f;
    #pragma unroll
    for (int i = 0; i < 4; i++) {
        v[i] = rp[i];
        mx = fmaxf(mx, fmaxf(fmaxf(fabsf(v[i].x), fabsf(v[i].y)),
                             fmaxf(fabsf(v[i].z), fabsf(v[i].w))));
    }
    smax[tid] = mx;
    __syncthreads();
    for (int s = 128; s > 0; s >>= 1) {
        if (tid < s) smax[tid] = fmaxf(smax[tid], smax[tid + s]);
        __syncthreads();
    }
    float s = fmaxf(smax[0], 1e-30f);
    float inv = 32512.f / s;

    int csum = 0;
    uint32_t hw[4], lw[4];
    #pragma unroll
    for (int i = 0; i < 4; i++) {
        float f[4] = {v[i].x, v[i].y, v[i].z, v[i].w};
        uint32_t h = 0, l = 0;
        #pragma unroll
        for (int j = 0; j < 4; j++) {
            int iv = __float2int_rn(f[j] * inv);
            int yh = (iv + 128) >> 8;
            int yl = iv - (yh << 8);
            csum += iv;
            h |= (uint32_t)(yh & 255) << (j * 8);
            l |= (uint32_t)(yl & 255) << (j * 8);
        }
        hw[i] = h; lw[i] = l;
    }
    *(uint4*)(qh + (size_t)re * N_NODES + tid * 16) = make_uint4(hw[0], hw[1], hw[2], hw[3]);
    *(uint4*)(ql + (size_t)re * N_NODES + tid * 16) = make_uint4(lw[0], lw[1], lw[2], lw[3]);

    ssum[tid] = csum;
    __syncthreads();
    for (int s2 = 128; s2 > 0; s2 >>= 1) {
        if (tid < s2) ssum[tid] += ssum[tid + s2];
        __syncthreads();
    }
    if (tid == 0) {
        float scf = s * (1.f / (32512.f * 32768.f));
        sc[re] = scf;
        cr[re] = 128.f * (float)ssum[0] * scf;
    }
}

// ---------------------------------------------------------------- int8 tensor GEMM
// part[r][n][e] = sum_m adj[r][n][m] * Y_r[m][e]
// CTA 128(M) x 64(N), 4 warps (2x2), warp tile 64x32, KC=128 (s8), 2-stage cp.async.
// Stage (48KB): Ah 128x128B @0, Al @16384, Bh 64x128B @32768, Bl @40960.
#define KC 128
#define STAGE_BYTES 49152

__device__ __forceinline__ void load_stage_i8(
    uint32_t sbase, int stage, int mt, int tid,
    const int8_t* Ahg, const int8_t* Alg,
    const int8_t* Bhg, const int8_t* Blg)
{
    const uint32_t st = sbase + stage * STAGE_BYTES;
    #pragma unroll
    for (int i = 0; i < 8; i++) {               // A: 1024 chunks per limb
        int c = tid + i * 128;
        int row = c >> 3, ch = c & 7;
        uint32_t dst = st + row * 128 + (((uint32_t)(ch ^ (row & 7))) << 4);
        size_t src = (size_t)row * N_NODES + mt + ch * 16;
        LDGSTS16(dst,         Ahg + src);
        LDGSTS16(dst + 16384, Alg + src);
    }
    #pragma unroll
    for (int i = 0; i < 4; i++) {               // B: 512 chunks per limb
        int c = tid + i * 128;
        int row = c >> 3, ch = c & 7;
        uint32_t dst = st + 32768 + row * 128 + (((uint32_t)(ch ^ (row & 7))) << 4);
        size_t src = (size_t)row * N_NODES + mt + ch * 16;
        LDGSTS16(dst,        Bhg + src);
        LDGSTS16(dst + 8192, Blg + src);
    }
}

__global__ void __launch_bounds__(128) gemm_i8_kernel(
    const int8_t* __restrict__ Ahg_all,
    const int8_t* __restrict__ Alg_all,
    const int8_t* __restrict__ Yqh,
    const int8_t* __restrict__ Yql,
    const float* __restrict__ scale,
    const float* __restrict__ corr,
    float* __restrict__ part)
{
    extern __shared__ __align__(16) char smem[];
    __shared__ float s_sc[64], s_cr[64];

    const int tid  = threadIdx.x;
    const int lane = tid & 31;
    const int wid  = tid >> 5;
    const int warp_m = wid & 1;    // 2 m-groups of 64
    const int warp_n = wid >> 1;   // 2 n-groups of 32
    const int n0 = blockIdx.x * 128;
    const int r  = blockIdx.y;
    const uint32_t sbase = smem_u32(smem);

    if (tid < 64) {
        s_sc[tid] = scale[r * HIDDEN + tid];
        s_cr[tid] = corr[r * HIDDEN + tid];
    }

    const int8_t* Ahg = Ahg_all + ((size_t)r * N_NODES + n0) * N_NODES;
    const int8_t* Alg = Alg_all + ((size_t)r * N_NODES + n0) * N_NODES;
    const int8_t* Bhg = Yqh + (size_t)r * HIDDEN * N_NODES;
    const int8_t* Blg = Yql + (size_t)r * HIDDEN * N_NODES;

    // ldmatrix lane geometry
    // A (m16k32 frag as 16x16 b16): groups: 0:rows+0-7,chunk+0 | 1:rows+8-15,+0 | 2:rows+0-7,+1 | 3:rows+8-15,+1
    const int a_row_l = ((lane >> 3) & 1) * 8 + (lane & 7);
    const int a_csel  = lane >> 4;             // chunk lsb
    // B (two n8k32 frags): 0:n+0-7,+0 | 1:n+0-7,+1 | 2:n+8-15,+0 | 3:n+8-15,+1
    const int b_row_l = (lane >> 4) * 8 + (lane & 7);
    const int b_csel  = (lane >> 3) & 1;

    int hh[4][4][4], mid[4][4][4];
    #pragma unroll
    for (int i = 0; i < 4; i++)
        #pragma unroll
        for (int j = 0; j < 4; j++)
            #pragma unroll
            for (int k = 0; k < 4; k++) { hh[i][j][k] = 0; mid[i][j][k] = 0; }

    load_stage_i8(sbase, 0, 0, tid, Ahg, Alg, Bhg, Blg);
    CP_COMMIT();

    #pragma unroll 1
    for (int it = 0; it < N_NODES / KC; ++it) {
        const int buf = it & 1;
        if (it < N_NODES / KC - 1) {
            load_stage_i8(sbase, buf ^ 1, (it + 1) * KC, tid, Ahg, Alg, Bhg, Blg);
            CP_COMMIT();
            CP_WAIT1();
        } else {
            CP_WAIT0();
        }
        __syncthreads();

        const uint32_t st = sbase + buf * STAGE_BYTES;
        #pragma unroll
        for (int kc = 0; kc < 4; kc++) {
            // B frags: [p][0..3] = b0/b1 of n-tile 2p, b0/b1 of n-tile 2p+1
            uint32_t bh[2][4], bl[2][4];
            #pragma unroll
            for (int p = 0; p < 2; p++) {
                int row = warp_n * 32 + p * 16 + b_row_l;
                uint32_t off = row * 128 + (((uint32_t)((kc * 2 + b_csel) ^ (row & 7))) << 4);
                LDSM4(bh[p], st + 32768 + off);
                LDSM4(bl[p], st + 40960 + off);
            }
            #pragma unroll
            for (int mi = 0; mi < 4; mi++) {
                int row = warp_m * 64 + mi * 16 + a_row_l;
                uint32_t off = row * 128 + (((uint32_t)((kc * 2 + a_csel) ^ (row & 7))) << 4);
                uint32_t ah[4], al[4];
                LDSM4(ah, st + off);
                LDSM4(al, st + 16384 + off);
                #pragma unroll
                for (int p = 0; p < 2; p++) {
                    #pragma unroll
                    for (int q = 0; q < 2; q++) {
                        const int nf = p * 2 + q;
                        MMAI8(hh[mi][nf],  ah, bh[p][q * 2], bh[p][q * 2 + 1]);
                        MMAI8(mid[mi][nf], ah, bl[p][q * 2], bl[p][q * 2 + 1]);
                        MMAI8(mid[mi][nf], al, bh[p][q * 2], bh[p][q * 2 + 1]);
                    }
                }
            }
        }
        __syncthreads();
    }

    // epilogue: out = sc[e]*(65536*hh + 256*mid) + cr[e]
    float* P = part + (size_t)r * NH;
    #pragma unroll
    for (int mi = 0; mi < 4; mi++) {
        const int row0 = n0 + warp_m * 64 + mi * 16 + (lane >> 2);
        #pragma unroll
        for (int nf = 0; nf < 4; nf++) {
            const int e0 = warp_n * 32 + nf * 8 + (lane & 3) * 2;
            float sc0 = s_sc[e0], sc1 = s_sc[e0 + 1];
            float cr0 = s_cr[e0], cr1 = s_cr[e0 + 1];
            float v0 = 65536.f * (float)hh[mi][nf][0] + 256.f * (float)mid[mi][nf][0];
            float v1 = 65536.f * (float)hh[mi][nf][1] + 256.f * (float)mid[mi][nf][1];
            float v2 = 65536.f * (float)hh[mi][nf][2] + 256.f * (float)mid[mi][nf][2];
            float v3 = 65536.f * (float)hh[mi][nf][3] + 256.f * (float)mid[mi][nf][3];
            *(float2*)&P[(size_t)row0 * HIDDEN + e0] =
                make_float2(fmaf(sc0, v0, cr0), fmaf(sc1, v1, cr1));
            *(float2*)&P[(size_t)(row0 + 8) * HIDDEN + e0] =
                make_float2(fmaf(sc0, v2, cr0), fmaf(sc1, v3, cr1));
        }
    }
}

// ---------------------------------------------------------------- finish
__global__ void finish_kernel(const float* __restrict__ S,
                              const float* __restrict__ part,
                              float* __restrict__ hn)
{
    int i = blockIdx.x * blockDim.x + threadIdx.x;
    if (i < NH) {
        float v = S[i];
        #pragma unroll
        for (int r = 0; r < N_REL; r++) v += part[(size_t)r * NH + i];
        hn[i] = fmaxf(v, 0.f);
    }
}

// ---------------------------------------------------------------- gather
__global__ void gather_kernel(const float* __restrict__ h,
                              const int* __restrict__ ids,
                              float* __restrict__ out)
{
    int k = blockIdx.x;
    int e = threadIdx.x;
    int id = ids[k];
    float v = (id < N_NODES) ? h[(size_t)id * HIDDEN + e] : 0.f;
    out[(size_t)k * HIDDEN + e] = v;
}

// ----------------------------------------------------------------
extern "C" void kernel_launch(void* const* d_in, const int* in_sizes, int n_in,
                              void* d_out, int out_size)
{
    const float* node_embed  = (const float*)d_in[0];
    const float* w_self      = (const float*)d_in[1];
    const float* w_rel       = (const float*)d_in[2];
    const float* rel_adj     = (const float*)d_in[3];
    const int*   keyword_ids = (const int*)d_in[4];
    float* out = (float*)d_out;

    float *h_base, *s_base, *p_base, *yt_base, *sc_base, *cr_base;
    int8_t *yqh_base, *yql_base, *ah_base, *al_base;
    cudaGetSymbolAddress((void**)&h_base, g_h);
    cudaGetSymbolAddress((void**)&s_base, g_S);
    cudaGetSymbolAddress((void**)&p_base, g_part);
    cudaGetSymbolAddress((void**)&yt_base, g_Yt);
    cudaGetSymbolAddress((void**)&sc_base, g_scale);
    cudaGetSymbolAddress((void**)&cr_base, g_corr);
    cudaGetSymbolAddress((void**)&yqh_base, g_Yqh);
    cudaGetSymbolAddress((void**)&yql_base, g_Yql);
    cudaGetSymbolAddress((void**)&ah_base, g_Ah);
    cudaGetSymbolAddress((void**)&al_base, g_Al);

    cudaFuncSetAttribute(gemm_i8_kernel,
                         cudaFuncAttributeMaxDynamicSharedMemorySize, 2 * STAGE_BYTES);

    copy_init_kernel<<<NH / 4 / 256, 256>>>(h_base, node_embed);
    convert_adj_kernel<<<32768, 256>>>(rel_adj, (uint32_t*)ah_base, (uint32_t*)al_base);

    for (int l = 0; l < N_LAYERS; l++) {
        float* hc = h_base + (size_t)(l & 1) * NH;
        float* hn = h_base + (size_t)((l + 1) & 1) * NH;
        compute_ys_kernel<<<dim3(64, 9), 256>>>(hc, w_self, w_rel, l, yt_base, s_base);
        quant_y_kernel<<<N_REL * HIDDEN, 256>>>(yt_base, yqh_base, yql_base, sc_base, cr_base);
        gemm_i8_kernel<<<dim3(32, N_REL), 128, 2 * STAGE_BYTES>>>(
            ah_base, al_base, yqh_base, yql_base, sc_base, cr_base, p_base);
        finish_kernel<<<NH / 256, 256>>>(s_base, p_base, hn);
    }

    gather_kernel<<<2048, 64>>>(h_base, keyword_ids, out);
}

// round 7
// speedup vs baseline: 1.0871x; 1.0871x over previous
#include <cuda_runtime.h>
#include <cuda_bf16.h>
#include <cstdint>

#define N_NODES 4096
#define HIDDEN  64
#define N_REL   8
#define N_LAYERS 2
#define NH (N_NODES * HIDDEN)

// ---------------------------------------------------------------- helpers
__device__ __forceinline__ uint32_t smem_u32(const void* p) {
    uint32_t a;
    asm("{ .reg .u64 t; cvta.to.shared.u64 t, %1; cvt.u32.u64 %0, t; }" : "=r"(a) : "l"(p));
    return a;
}

#define LDSM4(r, addr) \
    asm volatile("ldmatrix.sync.aligned.m8n8.x4.shared.b16 {%0,%1,%2,%3}, [%4];" \
        : "=r"((r)[0]), "=r"((r)[1]), "=r"((r)[2]), "=r"((r)[3]) : "r"(addr))

// int8 MMA: D(s32) += A(s8,16x32) * B(s8,32x8)
#define MMAI8(c, a, b0, b1) \
    asm volatile("mma.sync.aligned.m16n8k32.row.col.s32.s8.s8.s32 " \
        "{%0,%1,%2,%3}, {%4,%5,%6,%7}, {%8,%9}, {%0,%1,%2,%3};" \
        : "+r"((c)[0]), "+r"((c)[1]), "+r"((c)[2]), "+r"((c)[3]) \
        : "r"((a)[0]), "r"((a)[1]), "r"((a)[2]), "r"((a)[3]), "r"(b0), "r"(b1))

#define LDGSTS16(dst, src) \
    asm volatile("cp.async.cg.shared.global [%0], [%1], 16;" :: "r"(dst), "l"(src))
#define CP_COMMIT() asm volatile("cp.async.commit_group;" ::: "memory")
#define CP_WAIT1() asm volatile("cp.async.wait_group 1;" ::: "memory")
#define CP_WAIT0() asm volatile("cp.async.wait_group 0;" ::: "memory")

// ---------------------------------------------------------------- scratch
__device__ float g_h[2][NH];                               // g_h[l] = output of layer l
__device__ float g_S[NH];
__device__ float g_part[N_REL][NH];
__device__ float g_Yt[N_REL * HIDDEN * N_NODES];           // Y^T fp32 [r][e][m]
__device__ int8_t g_Yqh[N_REL * HIDDEN * N_NODES];         // Y^T hi limb
__device__ int8_t g_Yql[N_REL * HIDDEN * N_NODES];         // Y^T lo limb
__device__ float g_scale[N_REL * HIDDEN];
__device__ float g_corr[N_REL * HIDDEN];
__device__ int8_t g_Ah[(size_t)N_REL * N_NODES * N_NODES]; // adj hi limb
__device__ int8_t g_Al[(size_t)N_REL * N_NODES * N_NODES]; // adj lo limb ((q&255)-128)

// ---------------------------------------------------------------- adj -> s8 limbs (ONCE)
__global__ void __launch_bounds__(256) convert_adj_kernel(
    const float* __restrict__ adj,
    uint32_t* __restrict__ Ah,
    uint32_t* __restrict__ Al)
{
    size_t base = ((size_t)blockIdx.x * 256 + threadIdx.x) * 16;
    const float4* fp = (const float4*)(adj + base);
    uint32_t hw[4], lw[4];
    #pragma unroll
    for (int i = 0; i < 4; i++) {
        float4 f = fp[i];
        int q0 = min(32767, __float2int_rn(f.x * 32768.f));
        int q1 = min(32767, __float2int_rn(f.y * 32768.f));
        int q2 = min(32767, __float2int_rn(f.z * 32768.f));
        int q3 = min(32767, __float2int_rn(f.w * 32768.f));
        hw[i] = (uint32_t)(q0 >> 8) | ((uint32_t)(q1 >> 8) << 8) |
                ((uint32_t)(q2 >> 8) << 16) | ((uint32_t)(q3 >> 8) << 24);
        lw[i] = ((uint32_t)(q0 & 255) | ((uint32_t)(q1 & 255) << 8) |
                 ((uint32_t)(q2 & 255) << 16) | ((uint32_t)(q3 & 255) << 24)) ^ 0x80808080u;
    }
    *(uint4*)(Ah + base / 4) = make_uint4(hw[0], hw[1], hw[2], hw[3]);
    *(uint4*)(Al + base / 4) = make_uint4(lw[0], lw[1], lw[2], lw[3]);
}

// ---------------------------------------------------------------- Y / S
__global__ void __launch_bounds__(256) compute_ys_kernel(
    const float* __restrict__ h,
    const float* __restrict__ w_self,
    const float* __restrict__ w_rel,
    int layer,
    float* __restrict__ Yt,
    float* __restrict__ S)
{
    __shared__ float Ws[HIDDEN * HIDDEN];
    __shared__ float Hs[64 * HIDDEN];

    int m0 = blockIdx.x * 64;
    int wi = blockIdx.y;
    const float* W = (wi < N_REL)
        ? (w_rel + ((size_t)layer * N_REL + wi) * HIDDEN * HIDDEN)
        : (w_self + (size_t)layer * HIDDEN * HIDDEN);

    int tid = threadIdx.x;
    const float4* Wg = (const float4*)W;
    const float4* Hg = (const float4*)(h + (size_t)m0 * HIDDEN);
    for (int i = tid; i < 1024; i += 256) {
        ((float4*)Ws)[i] = Wg[i];
        ((float4*)Hs)[i] = Hg[i];
    }
    __syncthreads();

    int tx = tid & 15, ty = tid >> 4;
    int e0 = tx * 4;
    #pragma unroll
    for (int mi = 0; mi < 4; mi++) {
        int m = ty * 4 + mi;
        float4 acc = make_float4(0.f, 0.f, 0.f, 0.f);
        #pragma unroll
        for (int d = 0; d < HIDDEN; d++) {
            float hv = Hs[m * HIDDEN + d];
            float4 wv = *(const float4*)&Ws[d * HIDDEN + e0];
            acc.x = fmaf(hv, wv.x, acc.x);
            acc.y = fmaf(hv, wv.y, acc.y);
            acc.z = fmaf(hv, wv.z, acc.z);
            acc.w = fmaf(hv, wv.w, acc.w);
        }
        int mg = m0 + m;
        if (wi < N_REL) {
            float v[4] = {acc.x, acc.y, acc.z, acc.w};
            #pragma unroll
            for (int j = 0; j < 4; j++)
                Yt[((size_t)wi * HIDDEN + (e0 + j)) * N_NODES + mg] = v[j];
        } else {
            *(float4*)&S[(size_t)mg * HIDDEN + e0] = acc;
        }
    }
}

// ---------------------------------------------------------------- Y quantization
__global__ void __launch_bounds__(256) quant_y_kernel(
    const float* __restrict__ Yt,
    int8_t* __restrict__ qh, int8_t* __restrict__ ql,
    float* __restrict__ sc, float* __restrict__ cr)
{
    __shared__ float smax[256];
    __shared__ int ssum[256];
    int re = blockIdx.x;
    int tid = threadIdx.x;
    const float4* rp = (const float4*)(Yt + (size_t)re * N_NODES + tid * 16);

    float4 v[4];
    float mx = 0.f;
    #pragma unroll
    for (int i = 0; i < 4; i++) {
        v[i] = rp[i];
        mx = fmaxf(mx, fmaxf(fmaxf(fabsf(v[i].x), fabsf(v[i].y)),
                             fmaxf(fabsf(v[i].z), fabsf(v[i].w))));
    }
    smax[tid] = mx;
    __syncthreads();
    for (int s = 128; s > 0; s >>= 1) {
        if (tid < s) smax[tid] = fmaxf(smax[tid], smax[tid + s]);
        __syncthreads();
    }
    float s = fmaxf(smax[0], 1e-30f);
    float inv = 32512.f / s;

    int csum = 0;
    uint32_t hw[4], lw[4];
    #pragma unroll
    for (int i = 0; i < 4; i++) {
        float f[4] = {v[i].x, v[i].y, v[i].z, v[i].w};
        uint32_t h = 0, l = 0;
        #pragma unroll
        for (int j = 0; j < 4; j++) {
            int iv = __float2int_rn(f[j] * inv);
            int yh = (iv + 128) >> 8;
            int yl = iv - (yh << 8);
            csum += iv;
            h |= (uint32_t)(yh & 255) << (j * 8);
            l |= (uint32_t)(yl & 255) << (j * 8);
        }
        hw[i] = h; lw[i] = l;
    }
    *(uint4*)(qh + (size_t)re * N_NODES + tid * 16) = make_uint4(hw[0], hw[1], hw[2], hw[3]);
    *(uint4*)(ql + (size_t)re * N_NODES + tid * 16) = make_uint4(lw[0], lw[1], lw[2], lw[3]);

    ssum[tid] = csum;
    __syncthreads();
    for (int s2 = 128; s2 > 0; s2 >>= 1) {
        if (tid < s2) ssum[tid] += ssum[tid + s2];
        __syncthreads();
    }
    if (tid == 0) {
        float scf = s * (1.f / (32512.f * 32768.f));
        sc[re] = scf;
        cr[re] = 128.f * (float)ssum[0] * scf;
    }
}

// ---------------------------------------------------------------- int8 tensor GEMM
// CTA 128(M) x 64(N), 8 warps (4x2), warp tile 32x32, KC=128 s8, 2-stage cp.async.
// Stage (48KB): Ah 128x128B @0, Al @16384, Bh 64x128B @32768, Bl @40960.
#define KC 128
#define STAGE_BYTES 49152

__device__ __forceinline__ void load_stage_i8(
    uint32_t sbase, int stage, int mt, int tid,
    const int8_t* Ahg, const int8_t* Alg,
    const int8_t* Bhg, const int8_t* Blg)
{
    const uint32_t st = sbase + stage * STAGE_BYTES;
    #pragma unroll
    for (int i = 0; i < 4; i++) {               // A: 1024 chunks per limb
        int c = tid + i * 256;
        int row = c >> 3, ch = c & 7;
        uint32_t dst = st + row * 128 + (((uint32_t)(ch ^ (row & 7))) << 4);
        size_t src = (size_t)row * N_NODES + mt + ch * 16;
        LDGSTS16(dst,         Ahg + src);
        LDGSTS16(dst + 16384, Alg + src);
    }
    #pragma unroll
    for (int i = 0; i < 2; i++) {               // B: 512 chunks per limb
        int c = tid + i * 256;
        int row = c >> 3, ch = c & 7;
        uint32_t dst = st + 32768 + row * 128 + (((uint32_t)(ch ^ (row & 7))) << 4);
        size_t src = (size_t)row * N_NODES + mt + ch * 16;
        LDGSTS16(dst,        Bhg + src);
        LDGSTS16(dst + 8192, Blg + src);
    }
}

__global__ void __launch_bounds__(256, 2) gemm_i8_kernel(
    const int8_t* __restrict__ Ahg_all,
    const int8_t* __restrict__ Alg_all,
    const int8_t* __restrict__ Yqh,
    const int8_t* __restrict__ Yql,
    const float* __restrict__ scale,
    const float* __restrict__ corr,
    float* __restrict__ part)
{
    extern __shared__ __align__(16) char smem[];
    __shared__ float s_sc[64], s_cr[64];

    const int tid  = threadIdx.x;
    const int lane = tid & 31;
    const int wid  = tid >> 5;
    const int warp_m = wid & 3;    // 4 m-groups of 32
    const int warp_n = wid >> 2;   // 2 n-groups of 32
    const int n0 = blockIdx.x * 128;
    const int r  = blockIdx.y;
    const uint32_t sbase = smem_u32(smem);

    if (tid < 64) {
        s_sc[tid] = scale[r * HIDDEN + tid];
        s_cr[tid] = corr[r * HIDDEN + tid];
    }

    const int8_t* Ahg = Ahg_all + ((size_t)r * N_NODES + n0) * N_NODES;
    const int8_t* Alg = Alg_all + ((size_t)r * N_NODES + n0) * N_NODES;
    const int8_t* Bhg = Yqh + (size_t)r * HIDDEN * N_NODES;
    const int8_t* Blg = Yql + (size_t)r * HIDDEN * N_NODES;

    // ldmatrix lane geometry (validated by round-6 rel_err)
    const int a_row_l = ((lane >> 3) & 1) * 8 + (lane & 7);
    const int a_csel  = lane >> 4;
    const int b_row_l = (lane >> 4) * 8 + (lane & 7);
    const int b_csel  = (lane >> 3) & 1;

    int hh[2][4][4], mid[2][4][4];
    #pragma unroll
    for (int i = 0; i < 2; i++)
        #pragma unroll
        for (int j = 0; j < 4; j++)
            #pragma unroll
            for (int k = 0; k < 4; k++) { hh[i][j][k] = 0; mid[i][j][k] = 0; }

    load_stage_i8(sbase, 0, 0, tid, Ahg, Alg, Bhg, Blg);
    CP_COMMIT();

    #pragma unroll 1
    for (int it = 0; it < N_NODES / KC; ++it) {
        const int buf = it & 1;
        if (it < N_NODES / KC - 1) {
            load_stage_i8(sbase, buf ^ 1, (it + 1) * KC, tid, Ahg, Alg, Bhg, Blg);
            CP_COMMIT();
            CP_WAIT1();
        } else {
            CP_WAIT0();
        }
        __syncthreads();

        const uint32_t st = sbase + buf * STAGE_BYTES;
        #pragma unroll
        for (int kc = 0; kc < 4; kc++) {
            uint32_t bh[2][4], bl[2][4];
            #pragma unroll
            for (int p = 0; p < 2; p++) {
                int row = warp_n * 32 + p * 16 + b_row_l;
                uint32_t off = row * 128 + (((uint32_t)((kc * 2 + b_csel) ^ (row & 7))) << 4);
                LDSM4(bh[p], st + 32768 + off);
                LDSM4(bl[p], st + 40960 + off);
            }
            #pragma unroll
            for (int mi = 0; mi < 2; mi++) {
                int row = warp_m * 32 + mi * 16 + a_row_l;
                uint32_t off = row * 128 + (((uint32_t)((kc * 2 + a_csel) ^ (row & 7))) << 4);
                uint32_t ah[4], al[4];
                LDSM4(ah, st + off);
                LDSM4(al, st + 16384 + off);
                #pragma unroll
                for (int p = 0; p < 2; p++) {
                    #pragma unroll
                    for (int q = 0; q < 2; q++) {
                        const int nf = p * 2 + q;
                        MMAI8(hh[mi][nf],  ah, bh[p][q * 2], bh[p][q * 2 + 1]);
                        MMAI8(mid[mi][nf], ah, bl[p][q * 2], bl[p][q * 2 + 1]);
                        MMAI8(mid[mi][nf], al, bh[p][q * 2], bh[p][q * 2 + 1]);
                    }
                }
            }
        }
        __syncthreads();
    }

    // epilogue: out = sc[e]*(65536*hh + 256*mid) + cr[e]
    float* P = part + (size_t)r * NH;
    #pragma unroll
    for (int mi = 0; mi < 2; mi++) {
        const int row0 = n0 + warp_m * 32 + mi * 16 + (lane >> 2);
        #pragma unroll
        for (int nf = 0; nf < 4; nf++) {
            const int e0 = warp_n * 32 + nf * 8 + (lane & 3) * 2;
            float sc0 = s_sc[e0], sc1 = s_sc[e0 + 1];
            float cr0 = s_cr[e0], cr1 = s_cr[e0 + 1];
            float v0 = 65536.f * (float)hh[mi][nf][0] + 256.f * (float)mid[mi][nf][0];
            float v1 = 65536.f * (float)hh[mi][nf][1] + 256.f * (float)mid[mi][nf][1];
            float v2 = 65536.f * (float)hh[mi][nf][2] + 256.f * (float)mid[mi][nf][2];
            float v3 = 65536.f * (float)hh[mi][nf][3] + 256.f * (float)mid[mi][nf][3];
            *(float2*)&P[(size_t)row0 * HIDDEN + e0] =
                make_float2(fmaf(sc0, v0, cr0), fmaf(sc1, v1, cr1));
            *(float2*)&P[(size_t)(row0 + 8) * HIDDEN + e0] =
                make_float2(fmaf(sc0, v2, cr0), fmaf(sc1, v3, cr1));
        }
    }
}

// ---------------------------------------------------------------- finish
__global__ void finish_kernel(const float* __restrict__ S,
                              const float* __restrict__ part,
                              float* __restrict__ hn)
{
    int i = blockIdx.x * blockDim.x + threadIdx.x;
    if (i < NH) {
        float v = S[i];
        #pragma unroll
        for (int r = 0; r < N_REL; r++) v += part[(size_t)r * NH + i];
        hn[i] = fmaxf(v, 0.f);
    }
}

// ---------------------------------------------------------------- gather
__global__ void gather_kernel(const float* __restrict__ h,
                              const int* __restrict__ ids,
                              float* __restrict__ out)
{
    int k = blockIdx.x;
    int e = threadIdx.x;
    int id = ids[k];
    float v = (id < N_NODES) ? h[(size_t)id * HIDDEN + e] : 0.f;
    out[(size_t)k * HIDDEN + e] = v;
}

// ----------------------------------------------------------------
extern "C" void kernel_launch(void* const* d_in, const int* in_sizes, int n_in,
                              void* d_out, int out_size)
{
    const float* node_embed  = (const float*)d_in[0];
    const float* w_self      = (const float*)d_in[1];
    const float* w_rel       = (const float*)d_in[2];
    const float* rel_adj     = (const float*)d_in[3];
    const int*   keyword_ids = (const int*)d_in[4];
    float* out = (float*)d_out;

    float *h_base, *s_base, *p_base, *yt_base, *sc_base, *cr_base;
    int8_t *yqh_base, *yql_base, *ah_base, *al_base;
    cudaGetSymbolAddress((void**)&h_base, g_h);
    cudaGetSymbolAddress((void**)&s_base, g_S);
    cudaGetSymbolAddress((void**)&p_base, g_part);
    cudaGetSymbolAddress((void**)&yt_base, g_Yt);
    cudaGetSymbolAddress((void**)&sc_base, g_scale);
    cudaGetSymbolAddress((void**)&cr_base, g_corr);
    cudaGetSymbolAddress((void**)&yqh_base, g_Yqh);
    cudaGetSymbolAddress((void**)&yql_base, g_Yql);
    cudaGetSymbolAddress((void**)&ah_base, g_Ah);
    cudaGetSymbolAddress((void**)&al_base, g_Al);

    cudaFuncSetAttribute(gemm_i8_kernel,
                         cudaFuncAttributeMaxDynamicSharedMemorySize, 2 * STAGE_BYTES);

    convert_adj_kernel<<<32768, 256>>>(rel_adj, (uint32_t*)ah_base, (uint32_t*)al_base);

    for (int l = 0; l < N_LAYERS; l++) {
        const float* hc = (l == 0) ? node_embed : (h_base + (size_t)(l - 1) * NH);
        float* hn = h_base + (size_t)l * NH;
        compute_ys_kernel<<<dim3(64, 9), 256>>>(hc, w_self, w_rel, l, yt_base, s_base);
        quant_y_kernel<<<N_REL * HIDDEN, 256>>>(yt_base, yqh_base, yql_base, sc_base, cr_base);
        gemm_i8_kernel<<<dim3(32, N_REL), 256, 2 * STAGE_BYTES>>>(
            ah_base, al_base, yqh_base, yql_base, sc_base, cr_base, p_base);
        finish_kernel<<<NH / 256, 256>>>(s_base, p_base, hn);
    }

    gather_kernel<<<2048, 64>>>(h_base + NH, keyword_ids, out);
}

// round 8
// speedup vs baseline: 2.5739x; 2.3678x over previous
#include <cuda_runtime.h>
#include <cuda_bf16.h>
#include <cstdint>

#define N_NODES 4096
#define HIDDEN  64
#define N_REL   8
#define N_LAYERS 2
#define NH (N_NODES * HIDDEN)

// ---------------------------------------------------------------- helpers
__device__ __forceinline__ uint32_t smem_u32(const void* p) {
    uint32_t a;
    asm("{ .reg .u64 t; cvta.to.shared.u64 t, %1; cvt.u32.u64 %0, t; }" : "=r"(a) : "l"(p));
    return a;
}

// pack two floats into bf16x2 (f_even -> low half)
#define CVT_BF16X2(d, f_even, f_odd) \
    asm("cvt.rn.bf16x2.f32 %0, %1, %2;" : "=r"(d) : "f"(f_odd), "f"(f_even))

#define LDSM4(r, addr) \
    asm volatile("ldmatrix.sync.aligned.m8n8.x4.shared.b16 {%0,%1,%2,%3}, [%4];" \
        : "=r"((r)[0]), "=r"((r)[1]), "=r"((r)[2]), "=r"((r)[3]) : "r"(addr))

#define LDS64F(e, o, addr) \
    asm volatile("ld.shared.v2.f32 {%0,%1}, [%2];" : "=f"(e), "=f"(o) : "r"(addr))

#define MMA16816(c, a, b0, b1) \
    asm volatile("mma.sync.aligned.m16n8k16.row.col.f32.bf16.bf16.f32 " \
        "{%0,%1,%2,%3}, {%4,%5,%6,%7}, {%8,%9}, {%0,%1,%2,%3};" \
        : "+f"((c)[0]), "+f"((c)[1]), "+f"((c)[2]), "+f"((c)[3]) \
        : "r"((a)[0]), "r"((a)[1]), "r"((a)[2]), "r"((a)[3]), "r"(b0), "r"(b1))

#define LDGSTS16(dst, src) \
    asm volatile("cp.async.cg.shared.global [%0], [%1], 16;" :: "r"(dst), "l"(src))
#define CP_COMMIT() asm volatile("cp.async.commit_group;" ::: "memory")
#define CP_WAIT1() asm volatile("cp.async.wait_group 1;" ::: "memory")
#define CP_WAIT0() asm volatile("cp.async.wait_group 0;" ::: "memory")

// ---------------------------------------------------------------- scratch
__device__ float g_h[2][NH];                              // g_h[l] = output of layer l
__device__ float g_S[NH];
__device__ float g_part[N_REL][NH];
__device__ __nv_bfloat16 g_Yth[N_REL][HIDDEN][N_NODES];   // Y^T hi  [r][e][m]
__device__ __nv_bfloat16 g_Ytl[N_REL][HIDDEN][N_NODES];   // Y^T lo

// ---------------------------------------------------------------- Y / S
// wi<8: Yt limbs [wi][e][m] from h @ w_rel ; wi==8: S = h @ w_self (fp32)
__global__ void __launch_bounds__(256) compute_ys_kernel(
    const float* __restrict__ h,
    const float* __restrict__ w_self,
    const float* __restrict__ w_rel,
    int layer,
    __nv_bfloat16* __restrict__ Yth,
    __nv_bfloat16* __restrict__ Ytl,
    float* __restrict__ S)
{
    __shared__ float Ws[HIDDEN * HIDDEN];
    __shared__ float Hs[64 * HIDDEN];

    int m0 = blockIdx.x * 64;
    int wi = blockIdx.y;
    const float* W = (wi < N_REL)
        ? (w_rel + ((size_t)layer * N_REL + wi) * HIDDEN * HIDDEN)
        : (w_self + (size_t)layer * HIDDEN * HIDDEN);

    int tid = threadIdx.x;
    const float4* Wg = (const float4*)W;
    const float4* Hg = (const float4*)(h + (size_t)m0 * HIDDEN);
    for (int i = tid; i < 1024; i += 256) {
        ((float4*)Ws)[i] = Wg[i];
        ((float4*)Hs)[i] = Hg[i];
    }
    __syncthreads();

    int tx = tid & 15, ty = tid >> 4;
    int e0 = tx * 4;
    #pragma unroll
    for (int mi = 0; mi < 4; mi++) {
        int m = ty * 4 + mi;
        float4 acc = make_float4(0.f, 0.f, 0.f, 0.f);
        #pragma unroll
        for (int d = 0; d < HIDDEN; d++) {
            float hv = Hs[m * HIDDEN + d];
            float4 wv = *(const float4*)&Ws[d * HIDDEN + e0];
            acc.x = fmaf(hv, wv.x, acc.x);
            acc.y = fmaf(hv, wv.y, acc.y);
            acc.z = fmaf(hv, wv.z, acc.z);
            acc.w = fmaf(hv, wv.w, acc.w);
        }
        int mg = m0 + m;
        if (wi < N_REL) {
            float v[4] = {acc.x, acc.y, acc.z, acc.w};
            #pragma unroll
            for (int j = 0; j < 4; j++) {
                size_t idx = ((size_t)wi * HIDDEN + (e0 + j)) * N_NODES + mg;
                __nv_bfloat16 hi = __float2bfloat16_rn(v[j]);
                float res = v[j] - __bfloat162float(hi);
                Yth[idx] = hi;
                Ytl[idx] = __float2bfloat16_rn(res);
            }
        } else {
            *(float4*)&S[(size_t)mg * HIDDEN + e0] = acc;
        }
    }
}

// ---------------------------------------------------------------- pipelined tensor GEMM
// part[r][n][e] = sum_m adj[r][n][m] * Y_r[m][e]
// CTA 128(M) x 64(N), 8 warps (4x2), warp tile 32x32, KC=64, 2-stage cp.async.
// A tile kept as RAW FP32 in smem (rows of 64 fp32, padded stride 288B,
// chunk-XOR row&1 => conflict-free LDS.64 + STS). A-fragments are assembled
// per-lane via ld.shared.v2.f32 and split into bf16 hi/lo limbs in registers.
// B = Y^T hi/lo bf16 tiles, 128B rows, XOR swizzle (as validated in R5).
// Stage layout: A @0 (128*288 = 36864 B), Bh @36864 (8192), Bl @45056 (8192).
#define KC 64
#define A_STRIDE 288
#define BH_OFF 36864
#define BL_OFF 45056
#define STAGE_BYTES 53248

__device__ __forceinline__ void load_stage(
    uint32_t sbase, int stage, int mt, int tid,
    const float* Ag,
    const __nv_bfloat16* Bhg, const __nv_bfloat16* Blg)
{
    const uint32_t st = sbase + stage * STAGE_BYTES;
    // A: 128 rows x 64 fp32 = 2048 16B-chunks (16 per row)
    #pragma unroll
    for (int i = 0; i < 8; i++) {
        int c = tid + i * 256;
        int row = c >> 4, ch = c & 15;
        uint32_t dst = st + row * A_STRIDE + (((uint32_t)(ch ^ (row & 1))) << 4);
        const float* src = Ag + (size_t)row * N_NODES + mt + ch * 4;
        LDGSTS16(dst, src);
    }
    // B: 64 rows x 64 bf16 (128B rows) per limb = 512 chunks each
    #pragma unroll
    for (int i = 0; i < 2; i++) {
        int c = tid + i * 256;
        int row = c >> 3, ch = c & 7;
        uint32_t dst = st + row * 128 + (((uint32_t)(ch ^ (row & 7))) << 4);
        size_t src = (size_t)row * N_NODES + mt + ch * 8;
        LDGSTS16(dst + BH_OFF, Bhg + src);
        LDGSTS16(dst + BL_OFF, Blg + src);
    }
}

__global__ void __launch_bounds__(256, 2) gemm_pipe_kernel(
    const float* __restrict__ adj,
    const __nv_bfloat16* __restrict__ Yth,
    const __nv_bfloat16* __restrict__ Ytl,
    float* __restrict__ part)
{
    extern __shared__ __align__(16) char smem[];
    const int tid  = threadIdx.x;
    const int lane = tid & 31;
    const int wid  = tid >> 5;
    const int warp_m = wid & 3;
    const int warp_n = wid >> 2;
    const int n0 = blockIdx.x * 128;
    const int r  = blockIdx.y;
    const uint32_t sbase = smem_u32(smem);

    const float* Ag = adj + ((size_t)r << 24) + (size_t)(n0) * N_NODES;
    const __nv_bfloat16* Bhg = Yth + (size_t)r * HIDDEN * N_NODES;
    const __nv_bfloat16* Blg = Ytl + (size_t)r * HIDDEN * N_NODES;

    // A fragment lane geometry: for frag j, lane needs fp32 pair at
    //   row = warp_m*32 + mi*16 + (lane>>2) + (j&1)*8
    //   k   = ks*16 + (j>>1)*8 + (lane&3)*2
    const int a_g = lane >> 2;          // 0..7
    const int a_t2 = (lane & 3) * 2;    // k pair base

    // B ldmatrix lane geometry (identical to R5)
    const int b_row_l = (lane >> 4) * 8 + (lane & 7);
    const int b_csel  = (lane >> 3) & 1;

    float c[2][4][4];
    #pragma unroll
    for (int i = 0; i < 2; i++)
        #pragma unroll
        for (int j = 0; j < 4; j++)
            #pragma unroll
            for (int k = 0; k < 4; k++) c[i][j][k] = 0.f;

    load_stage(sbase, 0, 0, tid, Ag, Bhg, Blg);
    CP_COMMIT();

    #pragma unroll 1
    for (int it = 0; it < N_NODES / KC; ++it) {
        const int buf = it & 1;
        if (it < N_NODES / KC - 1) {
            load_stage(sbase, buf ^ 1, (it + 1) * KC, tid, Ag, Bhg, Blg);
            CP_COMMIT();
            CP_WAIT1();
        } else {
            CP_WAIT0();
        }
        __syncthreads();

        const uint32_t st = sbase + buf * STAGE_BYTES;
        #pragma unroll
        for (int ks = 0; ks < 4; ks++) {
            // ---- B fragments via ldmatrix (hi & lo limbs) ----
            uint32_t bh[2][4], bl[2][4];
            #pragma unroll
            for (int p = 0; p < 2; p++) {
                int brow = warp_n * 32 + p * 16 + b_row_l;
                uint32_t boff = brow * 128 +
                    (((uint32_t)((ks * 2 + b_csel) ^ (brow & 7))) << 4);
                LDSM4(bh[p], st + BH_OFF + boff);
                LDSM4(bl[p], st + BL_OFF + boff);
            }
            // ---- A fragments: LDS.64 fp32 pairs -> bf16 hi/lo split ----
            #pragma unroll
            for (int mi = 0; mi < 2; mi++) {
                uint32_t ah[4], al[4];
                #pragma unroll
                for (int j = 0; j < 4; j++) {
                    int row = warp_m * 32 + mi * 16 + a_g + (j & 1) * 8;
                    int k   = ks * 16 + ((j >> 1) << 3) + a_t2;
                    uint32_t addr = st + row * A_STRIDE +
                        (((uint32_t)((k >> 2) ^ (row & 1))) << 4) + (k & 3) * 4;
                    float e, o;
                    LDS64F(e, o, addr);
                    uint32_t h;
                    CVT_BF16X2(h, e, o);
                    ah[j] = h;
                    float re = e - __uint_as_float(h << 16);
                    float ro = o - __uint_as_float(h & 0xffff0000u);
                    CVT_BF16X2(al[j], re, ro);
                }
                #pragma unroll
                for (int p = 0; p < 2; p++) {
                    #pragma unroll
                    for (int q = 0; q < 2; q++) {
                        const int nf = p * 2 + q;
                        MMA16816(c[mi][nf], ah, bh[p][q * 2], bh[p][q * 2 + 1]);
                        MMA16816(c[mi][nf], al, bh[p][q * 2], bh[p][q * 2 + 1]);
                        MMA16816(c[mi][nf], ah, bl[p][q * 2], bl[p][q * 2 + 1]);
                    }
                }
            }
        }
        __syncthreads();
    }

    // epilogue
    float* P = part + (size_t)r * NH;
    #pragma unroll
    for (int mi = 0; mi < 2; mi++) {
        const int rbase = n0 + warp_m * 32 + mi * 16 + (lane >> 2);
        #pragma unroll
        for (int nf = 0; nf < 4; nf++) {
            const int cbase = warp_n * 32 + nf * 8 + (lane & 3) * 2;
            *(float2*)&P[(size_t)rbase * HIDDEN + cbase] =
                make_float2(c[mi][nf][0], c[mi][nf][1]);
            *(float2*)&P[(size_t)(rbase + 8) * HIDDEN + cbase] =
                make_float2(c[mi][nf][2], c[mi][nf][3]);
        }
    }
}

// ---------------------------------------------------------------- finish
__global__ void finish_kernel(const float* __restrict__ S,
                              const float* __restrict__ part,
                              float* __restrict__ hn)
{
    int i = blockIdx.x * blockDim.x + threadIdx.x;
    if (i < NH) {
        float v = S[i];
        #pragma unroll
        for (int r = 0; r < N_REL; r++) v += part[(size_t)r * NH + i];
        hn[i] = fmaxf(v, 0.f);
    }
}

// ---------------------------------------------------------------- gather
__global__ void gather_kernel(const float* __restrict__ h,
                              const int* __restrict__ ids,
                              float* __restrict__ out)
{
    int k = blockIdx.x;
    int e = threadIdx.x;
    int id = ids[k];
    float v = (id < N_NODES) ? h[(size_t)id * HIDDEN + e] : 0.f;
    out[(size_t)k * HIDDEN + e] = v;
}

// ----------------------------------------------------------------
extern "C" void kernel_launch(void* const* d_in, const int* in_sizes, int n_in,
                              void* d_out, int out_size)
{
    const float* node_embed  = (const float*)d_in[0];
    const float* w_self      = (const float*)d_in[1];
    const float* w_rel       = (const float*)d_in[2];
    const float* rel_adj     = (const float*)d_in[3];
    const int*   keyword_ids = (const int*)d_in[4];
    float* out = (float*)d_out;

    float *h_base, *s_base, *p_base;
    __nv_bfloat16 *yh_base, *yl_base;
    cudaGetSymbolAddress((void**)&h_base, g_h);
    cudaGetSymbolAddress((void**)&s_base, g_S);
    cudaGetSymbolAddress((void**)&p_base, g_part);
    cudaGetSymbolAddress((void**)&yh_base, g_Yth);
    cudaGetSymbolAddress((void**)&yl_base, g_Ytl);

    cudaFuncSetAttribute(gemm_pipe_kernel,
                         cudaFuncAttributeMaxDynamicSharedMemorySize, 2 * STAGE_BYTES);

    for (int l = 0; l < N_LAYERS; l++) {
        const float* hc = (l == 0) ? node_embed : (h_base + (size_t)(l - 1) * NH);
        float* hn = h_base + (size_t)l * NH;
        compute_ys_kernel<<<dim3(64, 9), 256>>>(hc, w_self, w_rel, l, yh_base, yl_base, s_base);
        gemm_pipe_kernel<<<dim3(32, N_REL), 256, 2 * STAGE_BYTES>>>(
            rel_adj, yh_base, yl_base, p_base);
        finish_kernel<<<NH / 256, 256>>>(s_base, p_base, hn);
    }

    gather_kernel<<<2048, 64>>>(h_base + NH, keyword_ids, out);
}

// round 9
// speedup vs baseline: 2.9498x; 1.1460x over previous
#include <cuda_runtime.h>
#include <cuda_bf16.h>
#include <cstdint>

#define N_NODES 4096
#define HIDDEN  64
#define N_REL   8
#define N_LAYERS 2
#define NH (N_NODES * HIDDEN)

// ---------------------------------------------------------------- helpers
__device__ __forceinline__ uint32_t smem_u32(const void* p) {
    uint32_t a;
    asm("{ .reg .u64 t; cvta.to.shared.u64 t, %1; cvt.u32.u64 %0, t; }" : "=r"(a) : "l"(p));
    return a;
}

// pack two floats into bf16x2 (f_even -> low half)
#define CVT_BF16X2(d, f_even, f_odd) \
    asm("cvt.rn.bf16x2.f32 %0, %1, %2;" : "=r"(d) : "f"(f_odd), "f"(f_even))

#define LDSM4(r, addr) \
    asm volatile("ldmatrix.sync.aligned.m8n8.x4.shared.b16 {%0,%1,%2,%3}, [%4];" \
        : "=r"((r)[0]), "=r"((r)[1]), "=r"((r)[2]), "=r"((r)[3]) : "r"(addr))

#define LDS64F(e, o, addr) \
    asm volatile("ld.shared.v2.f32 {%0,%1}, [%2];" : "=f"(e), "=f"(o) : "r"(addr))

#define MMA16816(c, a, b0, b1) \
    asm volatile("mma.sync.aligned.m16n8k16.row.col.f32.bf16.bf16.f32 " \
        "{%0,%1,%2,%3}, {%4,%5,%6,%7}, {%8,%9}, {%0,%1,%2,%3};" \
        : "+f"((c)[0]), "+f"((c)[1]), "+f"((c)[2]), "+f"((c)[3]) \
        : "r"((a)[0]), "r"((a)[1]), "r"((a)[2]), "r"((a)[3]), "r"(b0), "r"(b1))

#define LDGSTS16(dst, src) \
    asm volatile("cp.async.cg.shared.global [%0], [%1], 16;" :: "r"(dst), "l"(src))
#define CP_COMMIT() asm volatile("cp.async.commit_group;" ::: "memory")
#define CP_WAIT1() asm volatile("cp.async.wait_group 1;" ::: "memory")
#define CP_WAIT0() asm volatile("cp.async.wait_group 0;" ::: "memory")

// ---------------------------------------------------------------- scratch
__device__ float g_h[2][NH];                              // g_h[l] = output of layer l
__device__ float g_S[NH];
__device__ float g_part[N_REL][NH];
__device__ __nv_bfloat16 g_Yth[N_REL][HIDDEN][N_NODES];   // Y^T hi  [r][e][m]
__device__ __nv_bfloat16 g_Ytl[N_REL][HIDDEN][N_NODES];   // Y^T lo

// ---------------------------------------------------------------- Y / S
// wi<8: Y^T limbs [wi][e][m] from h @ w_rel (smem-transposed, coalesced stores)
// wi==8: S = h @ w_self (fp32, direct)
__global__ void __launch_bounds__(256) compute_ys_kernel(
    const float* __restrict__ h,
    const float* __restrict__ w_self,
    const float* __restrict__ w_rel,
    int layer,
    __nv_bfloat16* __restrict__ Yth,
    __nv_bfloat16* __restrict__ Ytl,
    float* __restrict__ S)
{
    // [0,4096) = W ; [4096,8192) = H ; Os aliases [4096, 8448) after phase 1
    __shared__ float sbuf[8448];
    float* Ws = sbuf;
    float* Hs = sbuf + 4096;
    float* Os = sbuf + 4096;

    int m0 = blockIdx.x * 64;
    int wi = blockIdx.y;
    const float* W = (wi < N_REL)
        ? (w_rel + ((size_t)layer * N_REL + wi) * HIDDEN * HIDDEN)
        : (w_self + (size_t)layer * HIDDEN * HIDDEN);

    int tid = threadIdx.x;
    const float4* Wg = (const float4*)W;
    const float4* Hg = (const float4*)(h + (size_t)m0 * HIDDEN);
    for (int i = tid; i < 1024; i += 256) {
        ((float4*)Ws)[i] = Wg[i];
        ((float4*)Hs)[i] = Hg[i];
    }
    __syncthreads();

    int tx = tid & 15, ty = tid >> 4;
    int e0 = tx * 4;
    float4 acc[4];
    #pragma unroll
    for (int mi = 0; mi < 4; mi++) {
        int m = ty * 4 + mi;
        float4 a = make_float4(0.f, 0.f, 0.f, 0.f);
        #pragma unroll
        for (int d = 0; d < HIDDEN; d++) {
            float hv = Hs[m * HIDDEN + d];
            float4 wv = *(const float4*)&Ws[d * HIDDEN + e0];
            a.x = fmaf(hv, wv.x, a.x);
            a.y = fmaf(hv, wv.y, a.y);
            a.z = fmaf(hv, wv.z, a.z);
            a.w = fmaf(hv, wv.w, a.w);
        }
        acc[mi] = a;
    }

    if (wi == N_REL) {
        #pragma unroll
        for (int mi = 0; mi < 4; mi++)
            *(float4*)&S[(size_t)(m0 + ty * 4 + mi) * HIDDEN + e0] = acc[mi];
        return;
    }

    // phase 2: transpose through smem, split limbs, coalesced 16B stores
    __syncthreads();                    // all Hs reads done -> safe to alias
    #pragma unroll
    for (int mi = 0; mi < 4; mi++)
        *(float4*)&Os[(ty * 4 + mi) * 68 + e0] = acc[mi];
    __syncthreads();

    int e   = tid >> 2;                 // 0..63
    int seg = tid & 3;                  // 16-m segment
    float v[16];
    #pragma unroll
    for (int i = 0; i < 16; i++)
        v[i] = Os[(seg * 16 + i) * 68 + e];

    uint32_t hw[8], lw[8];
    #pragma unroll
    for (int j = 0; j < 8; j++) {
        CVT_BF16X2(hw[j], v[2 * j], v[2 * j + 1]);
        float re = v[2 * j]     - __uint_as_float(hw[j] << 16);
        float ro = v[2 * j + 1] - __uint_as_float(hw[j] & 0xffff0000u);
        CVT_BF16X2(lw[j], re, ro);
    }
    size_t off = ((size_t)wi * HIDDEN + e) * N_NODES + m0 + seg * 16;
    *(uint4*)(Yth + off)     = make_uint4(hw[0], hw[1], hw[2], hw[3]);
    *(uint4*)(Yth + off + 8) = make_uint4(hw[4], hw[5], hw[6], hw[7]);
    *(uint4*)(Ytl + off)     = make_uint4(lw[0], lw[1], lw[2], lw[3]);
    *(uint4*)(Ytl + off + 8) = make_uint4(lw[4], lw[5], lw[6], lw[7]);
}

// ---------------------------------------------------------------- pipelined tensor GEMM
// (unchanged from round 8 — validated at ~157 us/layer)
#define KC 64
#define A_STRIDE 288
#define BH_OFF 36864
#define BL_OFF 45056
#define STAGE_BYTES 53248

__device__ __forceinline__ void load_stage(
    uint32_t sbase, int stage, int mt, int tid,
    const float* Ag,
    const __nv_bfloat16* Bhg, const __nv_bfloat16* Blg)
{
    const uint32_t st = sbase + stage * STAGE_BYTES;
    #pragma unroll
    for (int i = 0; i < 8; i++) {
        int c = tid + i * 256;
        int row = c >> 4, ch = c & 15;
        uint32_t dst = st + row * A_STRIDE + (((uint32_t)(ch ^ (row & 1))) << 4);
        const float* src = Ag + (size_t)row * N_NODES + mt + ch * 4;
        LDGSTS16(dst, src);
    }
    #pragma unroll
    for (int i = 0; i < 2; i++) {
        int c = tid + i * 256;
        int row = c >> 3, ch = c & 7;
        uint32_t dst = st + row * 128 + (((uint32_t)(ch ^ (row & 7))) << 4);
        size_t src = (size_t)row * N_NODES + mt + ch * 8;
        LDGSTS16(dst + BH_OFF, Bhg + src);
        LDGSTS16(dst + BL_OFF, Blg + src);
    }
}

__global__ void __launch_bounds__(256, 2) gemm_pipe_kernel(
    const float* __restrict__ adj,
    const __nv_bfloat16* __restrict__ Yth,
    const __nv_bfloat16* __restrict__ Ytl,
    float* __restrict__ part)
{
    extern __shared__ __align__(16) char smem[];
    const int tid  = threadIdx.x;
    const int lane = tid & 31;
    const int wid  = tid >> 5;
    const int warp_m = wid & 3;
    const int warp_n = wid >> 2;
    const int n0 = blockIdx.x * 128;
    const int r  = blockIdx.y;
    const uint32_t sbase = smem_u32(smem);

    const float* Ag = adj + ((size_t)r << 24) + (size_t)(n0) * N_NODES;
    const __nv_bfloat16* Bhg = Yth + (size_t)r * HIDDEN * N_NODES;
    const __nv_bfloat16* Blg = Ytl + (size_t)r * HIDDEN * N_NODES;

    const int a_g = lane >> 2;
    const int a_t2 = (lane & 3) * 2;
    const int b_row_l = (lane >> 4) * 8 + (lane & 7);
    const int b_csel  = (lane >> 3) & 1;

    float c[2][4][4];
    #pragma unroll
    for (int i = 0; i < 2; i++)
        #pragma unroll
        for (int j = 0; j < 4; j++)
            #pragma unroll
            for (int k = 0; k < 4; k++) c[i][j][k] = 0.f;

    load_stage(sbase, 0, 0, tid, Ag, Bhg, Blg);
    CP_COMMIT();

    #pragma unroll 1
    for (int it = 0; it < N_NODES / KC; ++it) {
        const int buf = it & 1;
        if (it < N_NODES / KC - 1) {
            load_stage(sbase, buf ^ 1, (it + 1) * KC, tid, Ag, Bhg, Blg);
            CP_COMMIT();
            CP_WAIT1();
        } else {
            CP_WAIT0();
        }
        __syncthreads();

        const uint32_t st = sbase + buf * STAGE_BYTES;
        #pragma unroll
        for (int ks = 0; ks < 4; ks++) {
            uint32_t bh[2][4], bl[2][4];
            #pragma unroll
            for (int p = 0; p < 2; p++) {
                int brow = warp_n * 32 + p * 16 + b_row_l;
                uint32_t boff = brow * 128 +
                    (((uint32_t)((ks * 2 + b_csel) ^ (brow & 7))) << 4);
                LDSM4(bh[p], st + BH_OFF + boff);
                LDSM4(bl[p], st + BL_OFF + boff);
            }
            #pragma unroll
            for (int mi = 0; mi < 2; mi++) {
                uint32_t ah[4], al[4];
                #pragma unroll
                for (int j = 0; j < 4; j++) {
                    int row = warp_m * 32 + mi * 16 + a_g + (j & 1) * 8;
                    int k   = ks * 16 + ((j >> 1) << 3) + a_t2;
                    uint32_t addr = st + row * A_STRIDE +
                        (((uint32_t)((k >> 2) ^ (row & 1))) << 4) + (k & 3) * 4;
                    float e, o;
                    LDS64F(e, o, addr);
                    uint32_t hq;
                    CVT_BF16X2(hq, e, o);
                    ah[j] = hq;
                    float re = e - __uint_as_float(hq << 16);
                    float ro = o - __uint_as_float(hq & 0xffff0000u);
                    CVT_BF16X2(al[j], re, ro);
                }
                #pragma unroll
                for (int p = 0; p < 2; p++) {
                    #pragma unroll
                    for (int q = 0; q < 2; q++) {
                        const int nf = p * 2 + q;
                        MMA16816(c[mi][nf], ah, bh[p][q * 2], bh[p][q * 2 + 1]);
                        MMA16816(c[mi][nf], al, bh[p][q * 2], bh[p][q * 2 + 1]);
                        MMA16816(c[mi][nf], ah, bl[p][q * 2], bl[p][q * 2 + 1]);
                    }
                }
            }
        }
        __syncthreads();
    }

    float* P = part + (size_t)r * NH;
    #pragma unroll
    for (int mi = 0; mi < 2; mi++) {
        const int rbase = n0 + warp_m * 32 + mi * 16 + (lane >> 2);
        #pragma unroll
        for (int nf = 0; nf < 4; nf++) {
            const int cbase = warp_n * 32 + nf * 8 + (lane & 3) * 2;
            *(float2*)&P[(size_t)rbase * HIDDEN + cbase] =
                make_float2(c[mi][nf][0], c[mi][nf][1]);
            *(float2*)&P[(size_t)(rbase + 8) * HIDDEN + cbase] =
                make_float2(c[mi][nf][2], c[mi][nf][3]);
        }
    }
}

// ---------------------------------------------------------------- finish
__global__ void finish_kernel(const float* __restrict__ S,
                              const float* __restrict__ part,
                              float* __restrict__ hn)
{
    int i = blockIdx.x * blockDim.x + threadIdx.x;
    if (i < NH) {
        float v = S[i];
        #pragma unroll
        for (int r = 0; r < N_REL; r++) v += part[(size_t)r * NH + i];
        hn[i] = fmaxf(v, 0.f);
    }
}

// ---------------------------------------------------------------- gather
__global__ void gather_kernel(const float* __restrict__ h,
                              const int* __restrict__ ids,
                              float* __restrict__ out)
{
    int k = blockIdx.x;
    int e = threadIdx.x;
    int id = ids[k];
    float v = (id < N_NODES) ? h[(size_t)id * HIDDEN + e] : 0.f;
    out[(size_t)k * HIDDEN + e] = v;
}

// ----------------------------------------------------------------
extern "C" void kernel_launch(void* const* d_in, const int* in_sizes, int n_in,
                              void* d_out, int out_size)
{
    const float* node_embed  = (const float*)d_in[0];
    const float* w_self      = (const float*)d_in[1];
    const float* w_rel       = (const float*)d_in[2];
    const float* rel_adj     = (const float*)d_in[3];
    const int*   keyword_ids = (const int*)d_in[4];
    float* out = (float*)d_out;

    float *h_base, *s_base, *p_base;
    __nv_bfloat16 *yh_base, *yl_base;
    cudaGetSymbolAddress((void**)&h_base, g_h);
    cudaGetSymbolAddress((void**)&s_base, g_S);
    cudaGetSymbolAddress((void**)&p_base, g_part);
    cudaGetSymbolAddress((void**)&yh_base, g_Yth);
    cudaGetSymbolAddress((void**)&yl_base, g_Ytl);

    cudaFuncSetAttribute(gemm_pipe_kernel,
                         cudaFuncAttributeMaxDynamicSharedMemorySize, 2 * STAGE_BYTES);

    for (int l = 0; l < N_LAYERS; l++) {
        const float* hc = (l == 0) ? node_embed : (h_base + (size_t)(l - 1) * NH);
        float* hn = h_base + (size_t)l * NH;
        compute_ys_kernel<<<dim3(64, 9), 256>>>(hc, w_self, w_rel, l, yh_base, yl_base, s_base);
        gemm_pipe_kernel<<<dim3(32, N_REL), 256, 2 * STAGE_BYTES>>>(
            rel_adj, yh_base, yl_base, p_base);
        finish_kernel<<<NH / 256, 256>>>(s_base, p_base, hn);
    }

    gather_kernel<<<2048, 64>>>(h_base + NH, keyword_ids, out);
}

// round 10
// speedup vs baseline: 3.2400x; 1.0984x over previous
#include <cuda_runtime.h>
#include <cuda_bf16.h>
#include <cstdint>

#define N_NODES 4096
#define HIDDEN  64
#define N_REL   8
#define N_LAYERS 2
#define NH (N_NODES * HIDDEN)

// ---------------------------------------------------------------- helpers
__device__ __forceinline__ uint32_t smem_u32(const void* p) {
    uint32_t a;
    asm("{ .reg .u64 t; cvta.to.shared.u64 t, %1; cvt.u32.u64 %0, t; }" : "=r"(a) : "l"(p));
    return a;
}

// pack two floats into bf16x2 (f_even -> low half)
#define CVT_BF16X2(d, f_even, f_odd) \
    asm("cvt.rn.bf16x2.f32 %0, %1, %2;" : "=r"(d) : "f"(f_odd), "f"(f_even))

#define LDSM4(r, addr) \
    asm volatile("ldmatrix.sync.aligned.m8n8.x4.shared.b16 {%0,%1,%2,%3}, [%4];" \
        : "=r"((r)[0]), "=r"((r)[1]), "=r"((r)[2]), "=r"((r)[3]) : "r"(addr))

#define LDS64F(e, o, addr) \
    asm volatile("ld.shared.v2.f32 {%0,%1}, [%2];" : "=f"(e), "=f"(o) : "r"(addr))

#define MMA16816(c, a, b0, b1) \
    asm volatile("mma.sync.aligned.m16n8k16.row.col.f32.bf16.bf16.f32 " \
        "{%0,%1,%2,%3}, {%4,%5,%6,%7}, {%8,%9}, {%0,%1,%2,%3};" \
        : "+f"((c)[0]), "+f"((c)[1]), "+f"((c)[2]), "+f"((c)[3]) \
        : "r"((a)[0]), "r"((a)[1]), "r"((a)[2]), "r"((a)[3]), "r"(b0), "r"(b1))

#define LDGSTS16(dst, src) \
    asm volatile("cp.async.cg.shared.global [%0], [%1], 16;" :: "r"(dst), "l"(src))
#define CP_COMMIT() asm volatile("cp.async.commit_group;" ::: "memory")
#define CP_WAIT1() asm volatile("cp.async.wait_group 1;" ::: "memory")
#define CP_WAIT0() asm volatile("cp.async.wait_group 0;" ::: "memory")

// ---------------------------------------------------------------- scratch
__device__ float g_h[2][NH];                              // g_h[l] = output of layer l
__device__ float g_S[NH];
__device__ float g_part[N_REL][NH];
__device__ __nv_bfloat16 g_Yth[N_REL][HIDDEN][N_NODES];   // Y^T hi  [r][e][m]
__device__ __nv_bfloat16 g_Ytl[N_REL][HIDDEN][N_NODES];   // Y^T lo

// ---------------------------------------------------------------- Y / S
__global__ void __launch_bounds__(256) compute_ys_kernel(
    const float* __restrict__ h,
    const float* __restrict__ w_self,
    const float* __restrict__ w_rel,
    int layer,
    __nv_bfloat16* __restrict__ Yth,
    __nv_bfloat16* __restrict__ Ytl,
    float* __restrict__ S)
{
    __shared__ float sbuf[8448];
    float* Ws = sbuf;
    float* Hs = sbuf + 4096;
    float* Os = sbuf + 4096;

    int m0 = blockIdx.x * 64;
    int wi = blockIdx.y;
    const float* W = (wi < N_REL)
        ? (w_rel + ((size_t)layer * N_REL + wi) * HIDDEN * HIDDEN)
        : (w_self + (size_t)layer * HIDDEN * HIDDEN);

    int tid = threadIdx.x;
    const float4* Wg = (const float4*)W;
    const float4* Hg = (const float4*)(h + (size_t)m0 * HIDDEN);
    for (int i = tid; i < 1024; i += 256) {
        ((float4*)Ws)[i] = Wg[i];
        ((float4*)Hs)[i] = Hg[i];
    }
    __syncthreads();

    int tx = tid & 15, ty = tid >> 4;
    int e0 = tx * 4;
    float4 acc[4];
    #pragma unroll
    for (int mi = 0; mi < 4; mi++) {
        int m = ty * 4 + mi;
        float4 a = make_float4(0.f, 0.f, 0.f, 0.f);
        #pragma unroll
        for (int d = 0; d < HIDDEN; d++) {
            float hv = Hs[m * HIDDEN + d];
            float4 wv = *(const float4*)&Ws[d * HIDDEN + e0];
            a.x = fmaf(hv, wv.x, a.x);
            a.y = fmaf(hv, wv.y, a.y);
            a.z = fmaf(hv, wv.z, a.z);
            a.w = fmaf(hv, wv.w, a.w);
        }
        acc[mi] = a;
    }

    if (wi == N_REL) {
        #pragma unroll
        for (int mi = 0; mi < 4; mi++)
            *(float4*)&S[(size_t)(m0 + ty * 4 + mi) * HIDDEN + e0] = acc[mi];
        return;
    }

    __syncthreads();
    #pragma unroll
    for (int mi = 0; mi < 4; mi++)
        *(float4*)&Os[(ty * 4 + mi) * 68 + e0] = acc[mi];
    __syncthreads();

    int e   = tid >> 2;
    int seg = tid & 3;
    float v[16];
    #pragma unroll
    for (int i = 0; i < 16; i++)
        v[i] = Os[(seg * 16 + i) * 68 + e];

    uint32_t hw[8], lw[8];
    #pragma unroll
    for (int j = 0; j < 8; j++) {
        CVT_BF16X2(hw[j], v[2 * j], v[2 * j + 1]);
        float re = v[2 * j]     - __uint_as_float(hw[j] << 16);
        float ro = v[2 * j + 1] - __uint_as_float(hw[j] & 0xffff0000u);
        CVT_BF16X2(lw[j], re, ro);
    }
    size_t off = ((size_t)wi * HIDDEN + e) * N_NODES + m0 + seg * 16;
    *(uint4*)(Yth + off)     = make_uint4(hw[0], hw[1], hw[2], hw[3]);
    *(uint4*)(Yth + off + 8) = make_uint4(hw[4], hw[5], hw[6], hw[7]);
    *(uint4*)(Ytl + off)     = make_uint4(lw[0], lw[1], lw[2], lw[3]);
    *(uint4*)(Ytl + off + 8) = make_uint4(lw[4], lw[5], lw[6], lw[7]);
}

// ---------------------------------------------------------------- pipelined tensor GEMM
// CTA 128(M) x 64(N), 4 warps, warp tile 32x64 (A read ONCE per element),
// KC=64, 2-stage cp.async, fp32 A in smem (split to bf16 limbs in regs).
#define KC 64
#define A_STRIDE 288
#define BH_OFF 36864
#define BL_OFF 45056
#define STAGE_BYTES 53248

__device__ __forceinline__ void load_stage(
    uint32_t sbase, int stage, int mt, int tid,
    const float* Ag,
    const __nv_bfloat16* Bhg, const __nv_bfloat16* Blg)
{
    const uint32_t st = sbase + stage * STAGE_BYTES;
    // A: 128 rows x 64 fp32 = 2048 16B-chunks; 16 per thread
    #pragma unroll
    for (int i = 0; i < 16; i++) {
        int c = tid + i * 128;
        int row = c >> 4, ch = c & 15;
        uint32_t dst = st + row * A_STRIDE + (((uint32_t)(ch ^ (row & 1))) << 4);
        const float* src = Ag + (size_t)row * N_NODES + mt + ch * 4;
        LDGSTS16(dst, src);
    }
    // B: 64 rows x 64 bf16 (128B rows) per limb = 512 chunks each; 4 per thread per limb
    #pragma unroll
    for (int i = 0; i < 4; i++) {
        int c = tid + i * 128;
        int row = c >> 3, ch = c & 7;
        uint32_t dst = st + row * 128 + (((uint32_t)(ch ^ (row & 7))) << 4);
        size_t src = (size_t)row * N_NODES + mt + ch * 8;
        LDGSTS16(dst + BH_OFF, Bhg + src);
        LDGSTS16(dst + BL_OFF, Blg + src);
    }
}

__global__ void __launch_bounds__(128, 2) gemm_pipe_kernel(
    const float* __restrict__ adj,
    const __nv_bfloat16* __restrict__ Yth,
    const __nv_bfloat16* __restrict__ Ytl,
    float* __restrict__ part)
{
    extern __shared__ __align__(16) char smem[];
    const int tid  = threadIdx.x;
    const int lane = tid & 31;
    const int warp_m = tid >> 5;        // 4 m-groups of 32; warp covers all 64 N
    const int n0 = blockIdx.x * 128;
    const int r  = blockIdx.y;
    const uint32_t sbase = smem_u32(smem);

    const float* Ag = adj + ((size_t)r << 24) + (size_t)(n0) * N_NODES;
    const __nv_bfloat16* Bhg = Yth + (size_t)r * HIDDEN * N_NODES;
    const __nv_bfloat16* Blg = Ytl + (size_t)r * HIDDEN * N_NODES;

    const int a_g = lane >> 2;
    const int a_t2 = (lane & 3) * 2;
    const int b_row_l = (lane >> 4) * 8 + (lane & 7);
    const int b_csel  = (lane >> 3) & 1;

    float c[2][8][4];
    #pragma unroll
    for (int i = 0; i < 2; i++)
        #pragma unroll
        for (int j = 0; j < 8; j++)
            #pragma unroll
            for (int k = 0; k < 4; k++) c[i][j][k] = 0.f;

    load_stage(sbase, 0, 0, tid, Ag, Bhg, Blg);
    CP_COMMIT();

    #pragma unroll 1
    for (int it = 0; it < N_NODES / KC; ++it) {
        const int buf = it & 1;
        if (it < N_NODES / KC - 1) {
            load_stage(sbase, buf ^ 1, (it + 1) * KC, tid, Ag, Bhg, Blg);
            CP_COMMIT();
            CP_WAIT1();
        } else {
            CP_WAIT0();
        }
        __syncthreads();

        const uint32_t st = sbase + buf * STAGE_BYTES;
        #pragma unroll
        for (int ks = 0; ks < 4; ks++) {
            // ---- B fragments (hi & lo limbs), 4 quads cover all 64 N ----
            uint32_t bh[4][4], bl[4][4];
            #pragma unroll
            for (int p = 0; p < 4; p++) {
                int brow = p * 16 + b_row_l;
                uint32_t boff = brow * 128 +
                    (((uint32_t)((ks * 2 + b_csel) ^ (brow & 7))) << 4);
                LDSM4(bh[p], st + BH_OFF + boff);
                LDSM4(bl[p], st + BL_OFF + boff);
            }
            // ---- A fragments: LDS.64 fp32 pairs -> bf16 hi/lo split ----
            #pragma unroll
            for (int mi = 0; mi < 2; mi++) {
                uint32_t ah[4], al[4];
                #pragma unroll
                for (int j = 0; j < 4; j++) {
                    int row = warp_m * 32 + mi * 16 + a_g + (j & 1) * 8;
                    int k   = ks * 16 + ((j >> 1) << 3) + a_t2;
                    uint32_t addr = st + row * A_STRIDE +
                        (((uint32_t)((k >> 2) ^ (row & 1))) << 4) + (k & 3) * 4;
                    float e, o;
                    LDS64F(e, o, addr);
                    uint32_t hq;
                    CVT_BF16X2(hq, e, o);
                    ah[j] = hq;
                    float re = e - __uint_as_float(hq << 16);
                    float ro = o - __uint_as_float(hq & 0xffff0000u);
                    CVT_BF16X2(al[j], re, ro);
                }
                #pragma unroll
                for (int p = 0; p < 4; p++) {
                    #pragma unroll
                    for (int q = 0; q < 2; q++) {
                        const int nf = p * 2 + q;
                        MMA16816(c[mi][nf], ah, bh[p][q * 2], bh[p][q * 2 + 1]);
                        MMA16816(c[mi][nf], al, bh[p][q * 2], bh[p][q * 2 + 1]);
                        MMA16816(c[mi][nf], ah, bl[p][q * 2], bl[p][q * 2 + 1]);
                    }
                }
            }
        }
        __syncthreads();
    }

    // epilogue
    float* P = part + (size_t)r * NH;
    #pragma unroll
    for (int mi = 0; mi < 2; mi++) {
        const int rbase = n0 + warp_m * 32 + mi * 16 + (lane >> 2);
        #pragma unroll
        for (int nf = 0; nf < 8; nf++) {
            const int cbase = nf * 8 + (lane & 3) * 2;
            *(float2*)&P[(size_t)rbase * HIDDEN + cbase] =
                make_float2(c[mi][nf][0], c[mi][nf][1]);
            *(float2*)&P[(size_t)(rbase + 8) * HIDDEN + cbase] =
                make_float2(c[mi][nf][2], c[mi][nf][3]);
        }
    }
}

// ---------------------------------------------------------------- finish
__global__ void finish_kernel(const float* __restrict__ S,
                              const float* __restrict__ part,
                              float* __restrict__ hn)
{
    int i = blockIdx.x * blockDim.x + threadIdx.x;
    if (i < NH) {
        float v = S[i];
        #pragma unroll
        for (int r = 0; r < N_REL; r++) v += part[(size_t)r * NH + i];
        hn[i] = fmaxf(v, 0.f);
    }
}

// ---------------------------------------------------------------- gather
__global__ void gather_kernel(const float* __restrict__ h,
                              const int* __restrict__ ids,
                              float* __restrict__ out)
{
    int k = blockIdx.x;
    int e = threadIdx.x;
    int id = ids[k];
    float v = (id < N_NODES) ? h[(size_t)id * HIDDEN + e] : 0.f;
    out[(size_t)k * HIDDEN + e] = v;
}

// ----------------------------------------------------------------
extern "C" void kernel_launch(void* const* d_in, const int* in_sizes, int n_in,
                              void* d_out, int out_size)
{
    const float* node_embed  = (const float*)d_in[0];
    const float* w_self      = (const float*)d_in[1];
    const float* w_rel       = (const float*)d_in[2];
    const float* rel_adj     = (const float*)d_in[3];
    const int*   keyword_ids = (const int*)d_in[4];
    float* out = (float*)d_out;

    float *h_base, *s_base, *p_base;
    __nv_bfloat16 *yh_base, *yl_base;
    cudaGetSymbolAddress((void**)&h_base, g_h);
    cudaGetSymbolAddress((void**)&s_base, g_S);
    cudaGetSymbolAddress((void**)&p_base, g_part);
    cudaGetSymbolAddress((void**)&yh_base, g_Yth);
    cudaGetSymbolAddress((void**)&yl_base, g_Ytl);

    cudaFuncSetAttribute(gemm_pipe_kernel,
                         cudaFuncAttributeMaxDynamicSharedMemorySize, 2 * STAGE_BYTES);

    for (int l = 0; l < N_LAYERS; l++) {
        const float* hc = (l == 0) ? node_embed : (h_base + (size_t)(l - 1) * NH);
        float* hn = h_base + (size_t)l * NH;
        compute_ys_kernel<<<dim3(64, 9), 256>>>(hc, w_self, w_rel, l, yh_base, yl_base, s_base);
        gemm_pipe_kernel<<<dim3(32, N_REL), 128, 2 * STAGE_BYTES>>>(
            rel_adj, yh_base, yl_base, p_base);
        finish_kernel<<<NH / 256, 256>>>(s_base, p_base, hn);
    }

    gather_kernel<<<2048, 64>>>(h_base + NH, keyword_ids, out);
}